// round 15
// baseline (speedup 1.0000x reference)
#include <cuda_runtime.h>
#include <math.h>
#include <stdint.h>

#define B   512
#define D   512
#define NC  1000
#define MM  200
#define KP  50
#define KN  20
#define NCKN (NC*KN)        // 20000 mem columns
#define NTOT (NCKN + B)     // 20512 = mem + batch columns
#define TEMPF   0.07f
#define MARGINF 0.5f

#define BM 128
#define BN 128
#define W  20               // u32 per smem row (16 data + 4 pad); 80B row stride
#define NIT 8               // 8 stages x 64 s8 = D=512
#define PD 3                // cp.async pipeline depth
#define NTN  ((NTOT + BN - 1) / BN)   // 161
#define TILE_TOT (NTN * (B / BM))     // 644
#define NCTA 296

// ---------------- device scratch ------------------------------------------------------
__device__ float g_f[B*D];
__device__ uint32_t g_a8[B*(D/4)];             // s8 packed normalized features (128 u32/row)
__device__ uint32_t g_b8[NCKN*(D/4)];          // s8 packed B rows (overrides applied)
__device__ float g_sa[B], g_sb[NCKN];          // per-row dequant scales (max/127)
__device__ int   g_rank[B], g_gsize[B], g_first[B];
__device__ unsigned long long g_ovmask[NC];    // deterministic across replays
__device__ int   g_ovrow[NC*KP];
__device__ float g_pos[B], g_all[B], g_hard[B];
__device__ int   g_hcnt[B], g_cntb[B];
__device__ int   g_ticket;
__device__ int   g_done;

// ---------------- helpers -------------------------------------------------------------
__device__ __forceinline__ void cpa16(uint32_t dst, const void* src) {
    asm volatile("cp.async.cg.shared.global [%0], [%1], 16;\n"
                 :: "r"(dst), "l"(__cvta_generic_to_global(src)));
}
#define CP_COMMIT() asm volatile("cp.async.commit_group;\n" ::: "memory")
#define CP_WAIT0()  asm volatile("cp.async.wait_group 0;\n" ::: "memory")
#define CP_WAIT1()  asm volatile("cp.async.wait_group 1;\n" ::: "memory")
#define LDSM4(r0, r1, r2, r3, addr) \
    asm volatile("ldmatrix.sync.aligned.m8n8.x4.shared.b16 {%0,%1,%2,%3}, [%4];" \
        : "=r"(r0), "=r"(r1), "=r"(r2), "=r"(r3) : "r"(addr))
#define MMA_S8(acc, a0, a1, a2, a3, b0, b1) \
    asm volatile("mma.sync.aligned.m16n8k32.row.col.s32.s8.s8.s32 " \
        "{%0,%1,%2,%3}, {%4,%5,%6,%7}, {%8,%9}, {%0,%1,%2,%3};\n" \
        : "+r"((acc)[0]), "+r"((acc)[1]), "+r"((acc)[2]), "+r"((acc)[3]) \
        : "r"(a0), "r"(a1), "r"(a2), "r"(a3), "r"(b0), "r"(b1))

// block max-reduce helper value via shared (caller provides 8-slot smem + sync)
// ---------------- prep: reset + normalize + s8 quant + stats --------------------------
__global__ void k_prep(const float* __restrict__ x, const int* __restrict__ labels,
                       const int* __restrict__ memptr) {
    int bid = blockIdx.x, tid = threadIdx.x;
    if (bid < B) {
        if (tid == 0) {
            g_pos[bid] = 0.f; g_all[bid] = 0.f; g_hard[bid] = 0.f;
            g_hcnt[bid] = 0;  g_cntb[bid] = 0;
            if (bid == 0) { g_ticket = 0; g_done = 0; }
        }
        const float2* xr2 = (const float2*)(x + (size_t)bid * D);
        float2 v = xr2[tid];
        float s = v.x * v.x + v.y * v.y;
        __shared__ float sm[8];
        #pragma unroll
        for (int o = 16; o; o >>= 1) s += __shfl_xor_sync(0xffffffffu, s, o);
        if ((tid & 31) == 0) sm[tid >> 5] = s;
        __syncthreads();
        if (tid == 0) {
            float t = 0.f;
            for (int w = 0; w < 8; w++) t += sm[w];
            sm[0] = t;
        }
        __syncthreads();
        float inv = 1.f / fmaxf(sqrtf(sm[0]), 1e-12f);
        float2 nv = { v.x * inv, v.y * inv };
        ((float2*)(g_f + (size_t)bid * D))[tid] = nv;
        __syncthreads();
        // row max for s8 quantization
        float m = fmaxf(fabsf(nv.x), fabsf(nv.y));
        #pragma unroll
        for (int o = 16; o; o >>= 1) m = fmaxf(m, __shfl_xor_sync(0xffffffffu, m, o));
        if ((tid & 31) == 0) sm[tid >> 5] = m;
        __syncthreads();
        if (tid == 0) {
            float t = sm[0];
            for (int w = 1; w < 8; w++) t = fmaxf(t, sm[w]);
            sm[0] = fmaxf(t, 1e-12f);
            g_sa[bid] = sm[0] * (1.f / 127.f);
        }
        __syncthreads();
        float qs = 127.f / sm[0];
        int qx = __float2int_rn(nv.x * qs);
        int qy = __float2int_rn(nv.y * qs);
        ((uint16_t*)g_a8)[(size_t)bid * (D / 2) + tid] =
            (uint16_t)((qx & 0xFF) | ((qy & 0xFF) << 8));
    } else {
        // stats: 2 blocks x 256 threads, 1 row per thread
        __shared__ int lab[B];
        lab[tid] = labels[tid];
        lab[tid + 256] = labels[tid + 256];
        __syncthreads();
        int i = (bid == B) ? tid : tid + 256;
        int li = lab[i];
        int r = 0, gs = 0, fi = B;
        #pragma unroll 4
        for (int j = 0; j < B; j++) {
            int e = (lab[j] == li);
            gs += e; r += e & (j < i);
            if (e && j < fi) fi = j;
        }
        g_rank[i] = r; g_gsize[i] = gs; g_first[i] = fi;
        int wp = (memptr[li] + r) % MM;
        if (wp < KP) {
            g_ovrow[li * KP + wp] = i;           // unique (li,wp): race-free
            atomicOr(&g_ovmask[li], 1ULL << wp); // idempotent across replays
        }
    }
}

// ---------------- conv: tail blocks first, then B-row s8 quantization -----------------
__global__ void k_conv(const float* __restrict__ memb, const int* __restrict__ labels) {
    int bid = blockIdx.x, tid = threadIdx.x;
    if (bid < B) {
        // ---- tail: own-class k in [KN,KP), fp32 exact; warp w -> kk = KN+w+8t ----
        int lane = tid & 31, warp = tid >> 5;
        int row = bid;
        int lb = labels[row];
        unsigned long long mask = g_ovmask[lb];
        const float4* fb4 = (const float4*)(g_f + (size_t)row * D);
        float4 a0 = fb4[lane], a1 = fb4[lane + 32],
               a2 = fb4[lane + 64], a3 = fb4[lane + 96];
        float local = 0.f;
        #pragma unroll
        for (int t = 0; t < 4; t++) {
            int kk = KN + warp + t * 8;
            if (kk < KP) {
                const float4* rp4 = ((mask >> kk) & 1ULL)
                    ? (const float4*)(g_f + (size_t)g_ovrow[lb * KP + kk] * D)
                    : (const float4*)(memb + ((size_t)lb * MM + kk) * D);
                float4 b0 = rp4[lane], b1 = rp4[lane + 32],
                       b2 = rp4[lane + 64], b3 = rp4[lane + 96];
                local += a0.x*b0.x + a0.y*b0.y + a0.z*b0.z + a0.w*b0.w
                       + a1.x*b1.x + a1.y*b1.y + a1.z*b1.z + a1.w*b1.w
                       + a2.x*b2.x + a2.y*b2.y + a2.z*b2.z + a2.w*b2.w
                       + a3.x*b3.x + a3.y*b3.y + a3.z*b3.z + a3.w*b3.w;
            }
        }
        #pragma unroll
        for (int o = 16; o; o >>= 1) local += __shfl_xor_sync(0xffffffffu, local, o);
        if (lane == 0 && local != 0.f) atomicAdd(&g_pos[row], local / TEMPF);
        return;
    }
    // ---- B-row s8 quantization: one row per block ----
    int ck = bid - B;
    int c = ck / KN, kk = ck - c * KN;
    const float* src;
    if ((g_ovmask[c] >> kk) & 1ULL)
        src = g_f + (size_t)g_ovrow[c * KP + kk] * D;
    else
        src = memb + ((size_t)c * MM + kk) * D;
    float2 v = ((const float2*)src)[tid];
    __shared__ float sm[8];
    float m = fmaxf(fabsf(v.x), fabsf(v.y));
    #pragma unroll
    for (int o = 16; o; o >>= 1) m = fmaxf(m, __shfl_xor_sync(0xffffffffu, m, o));
    if ((tid & 31) == 0) sm[tid >> 5] = m;
    __syncthreads();
    if (tid == 0) {
        float t = sm[0];
        for (int w = 1; w < 8; w++) t = fmaxf(t, sm[w]);
        sm[0] = fmaxf(t, 1e-12f);
        g_sb[ck] = sm[0] * (1.f / 127.f);
    }
    __syncthreads();
    float qs = 127.f / sm[0];
    int qx = __float2int_rn(v.x * qs);
    int qy = __float2int_rn(v.y * qs);
    ((uint16_t*)g_b8)[(size_t)ck * (D / 2) + tid] =
        (uint16_t)((qx & 0xFF) | ((qy & 0xFF) << 8));
}

// ---------------- persistent s8 IMMA GEMM + fused epilogue + last-CTA final -----------
__global__ __launch_bounds__(256, 2)
void k_gemm(const int* __restrict__ labels, float* __restrict__ out) {
    __shared__ uint32_t As[PD][BM][W];
    __shared__ uint32_t Bs[PD][BN][W];
    __shared__ float smSb[BN];
    __shared__ float smPos[BM], smAll[BM], smHard[BM];
    __shared__ int   smHc[BM], smCb[BM];
    __shared__ int   smTile, smLast;

    const int tid = threadIdx.x;
    const int lane = tid & 31, warp = tid >> 5;
    const int wm = (warp >> 2) * 64;
    const int wn = (warp & 3) * 32;
    const int g  = lane >> 2;
    const int tg = lane & 3;
    const uint32_t AsSh = (uint32_t)__cvta_generic_to_shared(As);
    const uint32_t BsSh = (uint32_t)__cvta_generic_to_shared(Bs);
    const int aRowL = ((lane >> 3) & 1) * 8 + (lane & 7);
    const int aColL = ((lane >> 4) & 1) * 4;
    const int bRowL = ((lane >> 4) & 1) * 8 + (lane & 7);
    const int bColL = ((lane >> 3) & 1) * 4;
    const bool isA = (tid < 128);
    const int lrow = tid & 127;
    const uint32_t dstBase = (isA ? AsSh : BsSh) + (uint32_t)(lrow * W * 4);

    for (;;) {
        if (tid == 0) smTile = atomicAdd(&g_ticket, 1);
        __syncthreads();
        const int tile = smTile;
        if (tile >= TILE_TOT) break;
        const int bm = (tile & 3) * BM;          // M fastest: B-tile L2 reuse
        const int bn = (tile >> 2) * BN;

        const uint32_t* srcRow;
        if (isA) {
            srcRow = g_a8 + (size_t)(bm + lrow) * (D / 4);
        } else {
            int ck = bn + lrow;
            if (ck < NCKN)        srcRow = g_b8 + (size_t)ck * (D / 4);
            else if (ck < NTOT)   srcRow = g_a8 + (size_t)(ck - NCKN) * (D / 4);
            else                  srcRow = g_a8;             // dummy for OOB
        }
        if (tid < BM) { smPos[tid] = 0.f; smAll[tid] = 0.f; smHard[tid] = 0.f;
                        smHc[tid] = 0; smCb[tid] = 0; }
        if (tid < BN) {
            int ck = bn + tid;
            smSb[tid] = (ck < NCKN) ? g_sb[ck]
                      : (ck < NTOT) ? g_sa[ck - NCKN] : 0.f;
        }
        __syncthreads();                         // smem reset + prev-tile drain

        int acc[4][4][4];
        #pragma unroll
        for (int i = 0; i < 4; i++)
            #pragma unroll
            for (int j = 0; j < 4; j++)
                #pragma unroll
                for (int q = 0; q < 4; q++) acc[i][j][q] = 0;

        #define ISSUE_STAGE(s, buf) do { \
            const uint32_t* sp = srcRow + (s) * 16; \
            uint32_t db = dstBase + (uint32_t)(buf) * (128 * W * 4); \
            cpa16(db,      sp); \
            cpa16(db + 16, sp + 4); \
            cpa16(db + 32, sp + 8); \
            cpa16(db + 48, sp + 12); \
            CP_COMMIT(); \
        } while (0)

        ISSUE_STAGE(0, 0);
        ISSUE_STAGE(1, 1);

        #pragma unroll 1
        for (int it = 0; it < NIT; it++) {
            const int p = it % PD;
            if (it >= NIT - 1) CP_WAIT0(); else CP_WAIT1();
            __syncthreads();
            if (it < NIT - 2) ISSUE_STAGE(it + 2, (it + 2) % PD);

            // ---- k-step 0 (u32 cols 0..7 = k 0..31 of stage) ----
            {
                uint32_t a[4][4], bq[2][4];
                #pragma unroll
                for (int mi = 0; mi < 4; mi++) {
                    uint32_t ad = AsSh + 4u * (uint32_t)(((p << 7) + wm + mi * 16 + aRowL) * W + aColL);
                    LDSM4(a[mi][0], a[mi][1], a[mi][2], a[mi][3], ad);
                }
                #pragma unroll
                for (int p2 = 0; p2 < 2; p2++) {
                    uint32_t bd = BsSh + 4u * (uint32_t)(((p << 7) + wn + p2 * 16 + bRowL) * W + bColL);
                    LDSM4(bq[p2][0], bq[p2][1], bq[p2][2], bq[p2][3], bd);
                }
                #pragma unroll
                for (int mi = 0; mi < 4; mi++)
                    #pragma unroll
                    for (int p2 = 0; p2 < 2; p2++) {
                        MMA_S8(acc[mi][2 * p2],     a[mi][0], a[mi][1], a[mi][2], a[mi][3], bq[p2][0], bq[p2][1]);
                        MMA_S8(acc[mi][2 * p2 + 1], a[mi][0], a[mi][1], a[mi][2], a[mi][3], bq[p2][2], bq[p2][3]);
                    }
            }
            // ---- k-step 1 (u32 cols 8..15 = k 32..63 of stage) ----
            {
                uint32_t a[4][4], bq[2][4];
                #pragma unroll
                for (int mi = 0; mi < 4; mi++) {
                    uint32_t ad = AsSh + 4u * (uint32_t)(((p << 7) + wm + mi * 16 + aRowL) * W + aColL + 8);
                    LDSM4(a[mi][0], a[mi][1], a[mi][2], a[mi][3], ad);
                }
                #pragma unroll
                for (int p2 = 0; p2 < 2; p2++) {
                    uint32_t bd = BsSh + 4u * (uint32_t)(((p << 7) + wn + p2 * 16 + bRowL) * W + bColL + 8);
                    LDSM4(bq[p2][0], bq[p2][1], bq[p2][2], bq[p2][3], bd);
                }
                #pragma unroll
                for (int mi = 0; mi < 4; mi++)
                    #pragma unroll
                    for (int p2 = 0; p2 < 2; p2++) {
                        MMA_S8(acc[mi][2 * p2],     a[mi][0], a[mi][1], a[mi][2], a[mi][3], bq[p2][0], bq[p2][1]);
                        MMA_S8(acc[mi][2 * p2 + 1], a[mi][0], a[mi][1], a[mi][2], a[mi][3], bq[p2][2], bq[p2][3]);
                    }
            }
        }
        #undef ISSUE_STAGE

        // ---- fused epilogue: dequant s = acc * sa[row] * sb[col] / TEMP ----
        #pragma unroll
        for (int mi = 0; mi < 4; mi++) {
            #pragma unroll
            for (int rr = 0; rr < 2; rr++) {
                int ml = wm + mi * 16 + g + rr * 8;
                int i = bm + ml;
                int lb = labels[i];
                int fi = g_first[i];
                int gs = g_gsize[i];
                float saT = g_sa[i] * (1.f / TEMPF);
                float pos = 0.f, alls = 0.f, hard = 0.f; int hc = 0, cb = 0;
                #pragma unroll
                for (int nj = 0; nj < 4; nj++) {
                    #pragma unroll
                    for (int q = 0; q < 2; q++) {
                        int cl = wn + nj * 8 + 2 * tg + q;
                        int ck = bn + cl;
                        float s = (float)acc[mi][nj][rr * 2 + q] * saT * smSb[cl];
                        if (ck < NCKN) {
                            int c = ck / KN;
                            if (c == lb) {
                                pos += s;
                            } else {
                                alls += s;
                                if (s > MARGINF) { hard += s; hc++; }
                            }
                        } else if (ck < NTOT) {
                            int j = ck - NCKN;
                            if (gs > 1 && labels[j] == lb && g_rank[j] != fi) {
                                pos += s; cb++;
                            }
                        }
                    }
                }
                if (pos  != 0.f) atomicAdd(&smPos[ml],  pos);   // add-0 == skip-0
                if (alls != 0.f) atomicAdd(&smAll[ml],  alls);
                if (hard != 0.f) atomicAdd(&smHard[ml], hard);
                if (hc)          atomicAdd(&smHc[ml],   hc);
                if (cb)          atomicAdd(&smCb[ml],   cb);
            }
        }
        __syncthreads();
        if (tid < BM) {
            int b = bm + tid;
            if (smPos[tid]  != 0.f) atomicAdd(&g_pos[b],  smPos[tid]);
            if (smAll[tid]  != 0.f) atomicAdd(&g_all[b],  smAll[tid]);
            if (smHard[tid] != 0.f) atomicAdd(&g_hard[b], smHard[tid]);
            if (smHc[tid])          atomicAdd(&g_hcnt[b], smHc[tid]);
            if (smCb[tid])          atomicAdd(&g_cntb[b], smCb[tid]);
        }
    }

    // ---- last-arriving CTA computes the final loss ----
    __syncthreads();
    if (tid == 0) {
        __threadfence();
        smLast = (atomicAdd(&g_done, 1) == NCTA - 1);
    }
    __syncthreads();
    if (smLast) {
        __threadfence();
        float* red = (float*)As;        // scratch: 256 floats
        float v = 0.f;
        for (int i = tid; i < B; i += 256) {
            float pl = -g_pos[i] / (float)(g_cntb[i] + KP);
            int hc = g_hcnt[i];
            float nl = (hc > 0) ? (g_hard[i] / (float)(hc > 1 ? hc : 1))
                                : (g_all[i] / (float)((NC - 1) * KN));
            v += pl + nl;
        }
        red[tid] = v;
        __syncthreads();
        for (int o = 128; o; o >>= 1) {
            if (tid < o) red[tid] += red[tid + o];
            __syncthreads();
        }
        if (tid == 0) out[0] = red[0] / (float)B;
    }
}

// ---------------- launch --------------------------------------------------------------
extern "C" void kernel_launch(void* const* d_in, const int* in_sizes, int n_in,
                              void* d_out, int out_size) {
    const float* features = (const float*)d_in[0];
    const int*   labels   = (const int*)d_in[1];
    const float* memb     = (const float*)d_in[2];
    const int*   memptr   = (const int*)d_in[3];
    float* out = (float*)d_out;

    k_prep<<<B + 2, 256>>>(features, labels, memptr);
    k_conv<<<B + NCKN, 256>>>(memb, labels);   // tail blocks first, then s8 quant
    k_gemm<<<NCTA, 256>>>(labels, out);        // persistent + last-CTA final
}

// round 16
// speedup vs baseline: 2.1838x; 2.1838x over previous
#include <cuda_runtime.h>
#include <math.h>
#include <stdint.h>

#define B   512
#define D   512
#define NC  1000
#define MM  200
#define KP  50
#define KN  20
#define NCKN (NC*KN)        // 20000 mem columns
#define NTOT (NCKN + B)     // 20512 = mem + batch columns
#define TEMPF   0.07f
#define MARGINF 0.5f

#define BM 128
#define BN 128
#define W  20               // u32 per smem row (16 data + 4 pad); 80B row stride
#define NIT 16              // 16 stages x 32 bf16 = D=512
#define PD 3                // cp.async pipeline depth
#define NTN  ((NTOT + BN - 1) / BN)   // 161
#define TILE_TOT (NTN * (B / BM))     // 644
#define NCTA 296
#define RPB 8               // conv: B-rows per block (one warp per row)
#define NCONV (NCKN / RPB)  // 2500 conversion blocks

// ---------------- device scratch ------------------------------------------------------
__device__ float g_f[B*D];
__device__ uint32_t g_a16[B*(D/2)];            // bf16x2 packed normalized features
__device__ uint32_t g_b16[NCKN*(D/2)];         // bf16x2 packed B rows (overrides applied)
__device__ int   g_rank[B], g_gsize[B], g_first[B];
__device__ unsigned long long g_ovmask[NC];    // deterministic across replays
__device__ int   g_ovrow[NC*KP];
__device__ float g_pos[B], g_all[B], g_hard[B];
__device__ int   g_hcnt[B], g_cntb[B];
__device__ int   g_ticket;
__device__ int   g_done;

// ---------------- helpers -------------------------------------------------------------
__device__ __forceinline__ uint32_t pack_bf16x2(float lo, float hi) {
    uint32_t r;
    asm("cvt.rn.bf16x2.f32 %0, %1, %2;" : "=r"(r) : "f"(hi), "f"(lo));
    return r;
}
__device__ __forceinline__ void cpa16(uint32_t dst, const void* src) {
    asm volatile("cp.async.cg.shared.global [%0], [%1], 16;\n"
                 :: "r"(dst), "l"(__cvta_generic_to_global(src)));
}
#define CP_COMMIT() asm volatile("cp.async.commit_group;\n" ::: "memory")
#define CP_WAIT0()  asm volatile("cp.async.wait_group 0;\n" ::: "memory")
#define CP_WAIT1()  asm volatile("cp.async.wait_group 1;\n" ::: "memory")
#define LDSM4(r0, r1, r2, r3, addr) \
    asm volatile("ldmatrix.sync.aligned.m8n8.x4.shared.b16 {%0,%1,%2,%3}, [%4];" \
        : "=r"(r0), "=r"(r1), "=r"(r2), "=r"(r3) : "r"(addr))
#define MMA_BF16(acc, a0, a1, a2, a3, b0, b1) \
    asm volatile("mma.sync.aligned.m16n8k16.row.col.f32.bf16.bf16.f32 " \
        "{%0,%1,%2,%3}, {%4,%5,%6,%7}, {%8,%9}, {%0,%1,%2,%3};\n" \
        : "+f"((acc)[0]), "+f"((acc)[1]), "+f"((acc)[2]), "+f"((acc)[3]) \
        : "r"(a0), "r"(a1), "r"(a2), "r"(a3), "r"(b0), "r"(b1))

// ---------------- prep: reset + normalize (f32 + bf16) + stats (2 blocks) -------------
__global__ void k_prep(const float* __restrict__ x, const int* __restrict__ labels,
                       const int* __restrict__ memptr) {
    int bid = blockIdx.x, tid = threadIdx.x;
    if (bid < B) {
        if (tid == 0) {
            g_pos[bid] = 0.f; g_all[bid] = 0.f; g_hard[bid] = 0.f;
            g_hcnt[bid] = 0;  g_cntb[bid] = 0;
            if (bid == 0) { g_ticket = 0; g_done = 0; }
        }
        const float2* xr2 = (const float2*)(x + (size_t)bid * D);
        float2 v = xr2[tid];                       // one float2 per thread covers the row
        float s = v.x * v.x + v.y * v.y;
        __shared__ float sm[8];
        #pragma unroll
        for (int o = 16; o; o >>= 1) s += __shfl_xor_sync(0xffffffffu, s, o);
        if ((tid & 31) == 0) sm[tid >> 5] = s;
        __syncthreads();
        if (tid == 0) {
            float t = 0.f;
            for (int w = 0; w < 8; w++) t += sm[w];
            sm[0] = t;
        }
        __syncthreads();
        float inv = 1.f / fmaxf(sqrtf(sm[0]), 1e-12f);
        float2 nv = { v.x * inv, v.y * inv };
        ((float2*)(g_f + (size_t)bid * D))[tid] = nv;
        g_a16[(size_t)bid * (D / 2) + tid] = pack_bf16x2(nv.x, nv.y);
    } else {
        // stats: 2 blocks x 256 threads, 1 row per thread
        __shared__ int lab[B];
        lab[tid] = labels[tid];
        lab[tid + 256] = labels[tid + 256];
        __syncthreads();
        int i = (bid == B) ? tid : tid + 256;
        int li = lab[i];
        int r = 0, gs = 0, fi = B;
        #pragma unroll 4
        for (int j = 0; j < B; j++) {
            int e = (lab[j] == li);
            gs += e; r += e & (j < i);
            if (e && j < fi) fi = j;
        }
        g_rank[i] = r; g_gsize[i] = gs; g_first[i] = fi;
        int wp = (memptr[li] + r) % MM;
        if (wp < KP) {
            g_ovrow[li * KP + wp] = i;           // unique (li,wp): race-free
            atomicOr(&g_ovmask[li], 1ULL << wp); // idempotent across replays
        }
    }
}

// ---------------- conv: tail blocks first, then B-row bf16 conversion (8 rows/blk) ----
__global__ void k_conv(const float* __restrict__ memb, const int* __restrict__ labels) {
    int bid = blockIdx.x, tid = threadIdx.x;
    int lane = tid & 31, warp = tid >> 5;
    if (bid < B) {
        // ---- tail: own-class k in [KN,KP), fp32 exact; warp w -> kk = KN+w+8t ----
        int row = bid;
        int lb = labels[row];
        unsigned long long mask = g_ovmask[lb];
        const float4* fb4 = (const float4*)(g_f + (size_t)row * D);
        float4 a0 = fb4[lane], a1 = fb4[lane + 32],
               a2 = fb4[lane + 64], a3 = fb4[lane + 96];
        float local = 0.f;
        #pragma unroll
        for (int t = 0; t < 4; t++) {
            int kk = KN + warp + t * 8;
            if (kk < KP) {
                const float4* rp4 = ((mask >> kk) & 1ULL)
                    ? (const float4*)(g_f + (size_t)g_ovrow[lb * KP + kk] * D)
                    : (const float4*)(memb + ((size_t)lb * MM + kk) * D);
                float4 b0 = rp4[lane], b1 = rp4[lane + 32],
                       b2 = rp4[lane + 64], b3 = rp4[lane + 96];
                local += a0.x*b0.x + a0.y*b0.y + a0.z*b0.z + a0.w*b0.w
                       + a1.x*b1.x + a1.y*b1.y + a1.z*b1.z + a1.w*b1.w
                       + a2.x*b2.x + a2.y*b2.y + a2.z*b2.z + a2.w*b2.w
                       + a3.x*b3.x + a3.y*b3.y + a3.z*b3.z + a3.w*b3.w;
            }
        }
        #pragma unroll
        for (int o = 16; o; o >>= 1) local += __shfl_xor_sync(0xffffffffu, local, o);
        if (lane == 0 && local != 0.f) atomicAdd(&g_pos[row], local / TEMPF);
        return;
    }
    // ---- B-row conversion: 8 rows per block, one warp per row, float4 MLP=4 ----
    int ck = (bid - B) * RPB + warp;
    int c = ck / KN, kk = ck - c * KN;
    const float4* src4;
    if ((g_ovmask[c] >> kk) & 1ULL)
        src4 = (const float4*)(g_f + (size_t)g_ovrow[c * KP + kk] * D);
    else
        src4 = (const float4*)(memb + ((size_t)c * MM + kk) * D);
    uint2* dst2 = (uint2*)(g_b16 + (size_t)ck * (D / 2));
    #pragma unroll
    for (int t = 0; t < 4; t++) {
        float4 v = src4[lane + t * 32];
        uint2 p = { pack_bf16x2(v.x, v.y), pack_bf16x2(v.z, v.w) };
        dst2[lane + t * 32] = p;
    }
}

// ---------------- persistent bf16 GEMM + fused epilogue + last-CTA final --------------
__global__ __launch_bounds__(256, 2)
void k_gemm(const int* __restrict__ labels, float* __restrict__ out) {
    __shared__ uint32_t As[PD][BM][W];
    __shared__ uint32_t Bs[PD][BN][W];
    __shared__ float smPos[BM], smAll[BM], smHard[BM];
    __shared__ int   smHc[BM], smCb[BM];
    __shared__ int   smTile, smLast;

    const int tid = threadIdx.x;
    const int lane = tid & 31, warp = tid >> 5;
    const int wm = (warp >> 2) * 64;
    const int wn = (warp & 3) * 32;
    const int g  = lane >> 2;
    const int tg = lane & 3;
    const uint32_t AsSh = (uint32_t)__cvta_generic_to_shared(As);
    const uint32_t BsSh = (uint32_t)__cvta_generic_to_shared(Bs);
    const int aRowL = ((lane >> 3) & 1) * 8 + (lane & 7);
    const int aColL = ((lane >> 4) & 1) * 4;
    const int bRowL = ((lane >> 4) & 1) * 8 + (lane & 7);
    const int bColL = ((lane >> 3) & 1) * 4;
    const bool isA = (tid < 128);
    const int lrow = tid & 127;
    const uint32_t dstBase = (isA ? AsSh : BsSh) + (uint32_t)(lrow * W * 4);

    for (;;) {
        if (tid == 0) smTile = atomicAdd(&g_ticket, 1);
        __syncthreads();
        const int tile = smTile;
        if (tile >= TILE_TOT) break;
        const int bm = (tile & 3) * BM;          // M fastest: B-tile L2 reuse
        const int bn = (tile >> 2) * BN;

        const uint32_t* srcRow;
        if (isA) {
            srcRow = g_a16 + (size_t)(bm + lrow) * (D / 2);
        } else {
            int ck = bn + lrow;
            if (ck < NCKN)        srcRow = g_b16 + (size_t)ck * (D / 2);
            else if (ck < NTOT)   srcRow = g_a16 + (size_t)(ck - NCKN) * (D / 2);
            else                  srcRow = g_a16;             // dummy for OOB
        }
        if (tid < BM) { smPos[tid] = 0.f; smAll[tid] = 0.f; smHard[tid] = 0.f;
                        smHc[tid] = 0; smCb[tid] = 0; }
        __syncthreads();                         // smem reset + prev-tile drain

        float acc[4][4][4];
        #pragma unroll
        for (int i = 0; i < 4; i++)
            #pragma unroll
            for (int j = 0; j < 4; j++)
                #pragma unroll
                for (int q = 0; q < 4; q++) acc[i][j][q] = 0.f;

        #define ISSUE_STAGE(s, buf) do { \
            const uint32_t* sp = srcRow + (s) * 16; \
            uint32_t db = dstBase + (uint32_t)(buf) * (128 * W * 4); \
            cpa16(db,      sp); \
            cpa16(db + 16, sp + 4); \
            cpa16(db + 32, sp + 8); \
            cpa16(db + 48, sp + 12); \
            CP_COMMIT(); \
        } while (0)

        ISSUE_STAGE(0, 0);
        ISSUE_STAGE(1, 1);

        #pragma unroll 1
        for (int it = 0; it < NIT; it++) {
            const int p = it % PD;
            if (it >= NIT - 1) CP_WAIT0(); else CP_WAIT1();
            __syncthreads();
            if (it < NIT - 2) ISSUE_STAGE(it + 2, (it + 2) % PD);

            // ---- k-step 0 (u32 cols 0..7) ----
            {
                uint32_t a[4][4], bq[2][4];
                #pragma unroll
                for (int mi = 0; mi < 4; mi++) {
                    uint32_t ad = AsSh + 4u * (uint32_t)(((p << 7) + wm + mi * 16 + aRowL) * W + aColL);
                    LDSM4(a[mi][0], a[mi][1], a[mi][2], a[mi][3], ad);
                }
                #pragma unroll
                for (int p2 = 0; p2 < 2; p2++) {
                    uint32_t bd = BsSh + 4u * (uint32_t)(((p << 7) + wn + p2 * 16 + bRowL) * W + bColL);
                    LDSM4(bq[p2][0], bq[p2][1], bq[p2][2], bq[p2][3], bd);
                }
                #pragma unroll
                for (int mi = 0; mi < 4; mi++)
                    #pragma unroll
                    for (int p2 = 0; p2 < 2; p2++) {
                        MMA_BF16(acc[mi][2 * p2],     a[mi][0], a[mi][1], a[mi][2], a[mi][3], bq[p2][0], bq[p2][1]);
                        MMA_BF16(acc[mi][2 * p2 + 1], a[mi][0], a[mi][1], a[mi][2], a[mi][3], bq[p2][2], bq[p2][3]);
                    }
            }
            // ---- k-step 1 (u32 cols 8..15) ----
            {
                uint32_t a[4][4], bq[2][4];
                #pragma unroll
                for (int mi = 0; mi < 4; mi++) {
                    uint32_t ad = AsSh + 4u * (uint32_t)(((p << 7) + wm + mi * 16 + aRowL) * W + aColL + 8);
                    LDSM4(a[mi][0], a[mi][1], a[mi][2], a[mi][3], ad);
                }
                #pragma unroll
                for (int p2 = 0; p2 < 2; p2++) {
                    uint32_t bd = BsSh + 4u * (uint32_t)(((p << 7) + wn + p2 * 16 + bRowL) * W + bColL + 8);
                    LDSM4(bq[p2][0], bq[p2][1], bq[p2][2], bq[p2][3], bd);
                }
                #pragma unroll
                for (int mi = 0; mi < 4; mi++)
                    #pragma unroll
                    for (int p2 = 0; p2 < 2; p2++) {
                        MMA_BF16(acc[mi][2 * p2],     a[mi][0], a[mi][1], a[mi][2], a[mi][3], bq[p2][0], bq[p2][1]);
                        MMA_BF16(acc[mi][2 * p2 + 1], a[mi][0], a[mi][1], a[mi][2], a[mi][3], bq[p2][2], bq[p2][3]);
                    }
            }
        }
        #undef ISSUE_STAGE

        // ---- fused epilogue ----
        #pragma unroll
        for (int mi = 0; mi < 4; mi++) {
            #pragma unroll
            for (int rr = 0; rr < 2; rr++) {
                int ml = wm + mi * 16 + g + rr * 8;
                int i = bm + ml;
                int lb = labels[i];
                int fi = g_first[i];
                int gs = g_gsize[i];
                float pos = 0.f, alls = 0.f, hard = 0.f; int hc = 0, cb = 0;
                #pragma unroll
                for (int nj = 0; nj < 4; nj++) {
                    #pragma unroll
                    for (int q = 0; q < 2; q++) {
                        int ck = bn + wn + nj * 8 + 2 * tg + q;
                        float s = acc[mi][nj][rr * 2 + q] / TEMPF;
                        if (ck < NCKN) {
                            int c = ck / KN;
                            if (c == lb) {
                                pos += s;
                            } else {
                                alls += s;
                                if (s > MARGINF) { hard += s; hc++; }
                            }
                        } else if (ck < NTOT) {
                            int j = ck - NCKN;
                            if (gs > 1 && labels[j] == lb && g_rank[j] != fi) {
                                pos += s; cb++;
                            }
                        }
                    }
                }
                if (pos  != 0.f) atomicAdd(&smPos[ml],  pos);   // add-0 == skip-0
                if (alls != 0.f) atomicAdd(&smAll[ml],  alls);
                if (hard != 0.f) atomicAdd(&smHard[ml], hard);
                if (hc)          atomicAdd(&smHc[ml],   hc);
                if (cb)          atomicAdd(&smCb[ml],   cb);
            }
        }
        __syncthreads();
        if (tid < BM) {
            int b = bm + tid;
            if (smPos[tid]  != 0.f) atomicAdd(&g_pos[b],  smPos[tid]);
            if (smAll[tid]  != 0.f) atomicAdd(&g_all[b],  smAll[tid]);
            if (smHard[tid] != 0.f) atomicAdd(&g_hard[b], smHard[tid]);
            if (smHc[tid])          atomicAdd(&g_hcnt[b], smHc[tid]);
            if (smCb[tid])          atomicAdd(&g_cntb[b], smCb[tid]);
        }
    }

    // ---- last-arriving CTA computes the final loss ----
    __syncthreads();
    if (tid == 0) {
        __threadfence();
        smLast = (atomicAdd(&g_done, 1) == NCTA - 1);
    }
    __syncthreads();
    if (smLast) {
        __threadfence();
        float* red = (float*)As;        // scratch: 256 floats
        float v = 0.f;
        for (int i = tid; i < B; i += 256) {
            float pl = -g_pos[i] / (float)(g_cntb[i] + KP);
            int hc = g_hcnt[i];
            float nl = (hc > 0) ? (g_hard[i] / (float)(hc > 1 ? hc : 1))
                                : (g_all[i] / (float)((NC - 1) * KN));
            v += pl + nl;
        }
        red[tid] = v;
        __syncthreads();
        for (int o = 128; o; o >>= 1) {
            if (tid < o) red[tid] += red[tid + o];
            __syncthreads();
        }
        if (tid == 0) out[0] = red[0] / (float)B;
    }
}

// ---------------- launch --------------------------------------------------------------
extern "C" void kernel_launch(void* const* d_in, const int* in_sizes, int n_in,
                              void* d_out, int out_size) {
    const float* features = (const float*)d_in[0];
    const int*   labels   = (const int*)d_in[1];
    const float* memb     = (const float*)d_in[2];
    const int*   memptr   = (const int*)d_in[3];
    float* out = (float*)d_out;

    k_prep<<<B + 2, 256>>>(features, labels, memptr);
    k_conv<<<B + NCONV, 256>>>(memb, labels);  // tail blocks first, then 8-row conv blocks
    k_gemm<<<NCTA, 256>>>(labels, out);        // persistent + last-CTA final
}